// round 5
// baseline (speedup 1.0000x reference)
#include <cuda_runtime.h>
#include <cuda_fp16.h>
#include <math.h>
#include <stdint.h>

// Problem constants (fixed by the dataset)
#define TT 5
#define FIN 10
#define HID 16
#define MAXN 100000
#define MAXE 3200000
#define XSTRIDE 52        // padded T*FIN in halves (50 -> 52; pad stays zero)
#define XREAL  50
#define FSTRIDE 80        // T*HID

// ---------------- device scratch (static: no allocation allowed) ----------------
__device__ int    g_cnt[MAXN];         // zero at load; re-zeroed each call in koffsets
__device__ int    g_deg[MAXN];
__device__ int    g_row[MAXN];
__device__ int    g_cursor[MAXN];
__device__ int    g_total;
__device__ float  g_dis[MAXN];
__device__ float  g_dinv[MAXN];
__device__ __align__(16) int2   g_edge[MAXE];   // .x = src, .y = half2(w,w) bits
__device__ __align__(16) __half g_xT[(size_t)MAXN * XSTRIDE];
__device__ __align__(16) __half g_h1[(size_t)MAXN * FSTRIDE];
__device__ __align__(16) __half g_feats[(size_t)MAXN * FSTRIDE];
__device__ __align__(16) __half g_P[(size_t)MAXN * FSTRIDE];
__device__ float  g_Mz[256], g_Mr[256], g_Mh[256];
__device__ float  g_Bz[16],  g_Br[16],  g_Bh[16];

__device__ __forceinline__ __half2 bits_h2(int b) {
    return *reinterpret_cast<__half2*>(&b);
}
__device__ __forceinline__ __half2 bits_h2u(unsigned b) {
    return *reinterpret_cast<__half2*>(&b);
}
__device__ __forceinline__ float fast_tanh(float x) {
    float r;
    asm("tanh.approx.f32 %0, %1;" : "=f"(r) : "f"(x));
    return r;
}
__device__ __forceinline__ float fast_sig(float x) {
    return fmaf(0.5f, fast_tanh(0.5f * x), 0.5f);
}

// ---------------- stage 0: fused degree count + x transpose (fp16) --------------
__global__ void kprep0(const int* __restrict__ dst, int* cnt,
                       const float* __restrict__ x, __half* __restrict__ xT,
                       int n, int e) {
    int i = blockIdx.x * blockDim.x + threadIdx.x;
    if (i == 0) g_total = 0;
    if (i < e) atomicAdd(&cnt[dst[i]], 1);
    if (i < n * XREAL) {
        int node = i / XREAL;
        int c = i - node * XREAL;
        int t = c / FIN;
        int f = c - t * FIN;
        xT[(size_t)node * XSTRIDE + c] =
            __float2half(x[((size_t)t * n + node) * FIN + f]);
    }
}

// per-block scan + single atomic -> contiguous (unordered) slices per node
__global__ __launch_bounds__(256) void koffsets(int* cnt, int n) {
    __shared__ int sh[256];
    __shared__ int sbase;
    int tid = threadIdx.x;
    int i = blockIdx.x * 256 + tid;
    int deg = (i < n) ? cnt[i] : 0;
    sh[tid] = deg;
    __syncthreads();
    for (int off = 1; off < 256; off <<= 1) {
        int t = (tid >= off) ? sh[tid - off] : 0;
        __syncthreads();
        sh[tid] += t;
        __syncthreads();
    }
    if (tid == 255) sbase = atomicAdd(&g_total, sh[255]);
    __syncthreads();
    int start = sbase + sh[tid] - deg;
    if (i < n) {
        g_row[i]    = start;
        g_cursor[i] = start;
        g_deg[i]    = deg;
        cnt[i]      = 0;                 // restore for next replay
        float d = (float)deg + 1.0f;
        g_dis[i]  = rsqrtf(d);
        g_dinv[i] = 1.0f / d;
    }
}

__global__ void kfill(const int* __restrict__ src, const int* __restrict__ dst,
                      const float* __restrict__ dis, int* cursor, int2* edge, int e) {
    int i = blockIdx.x * blockDim.x + threadIdx.x;
    if (i < e) {
        int s = src[i], d = dst[i];
        int pos = atomicAdd(&cursor[d], 1);
        __half2 h2 = __float2half2_rn(dis[s] * dis[d]);
        edge[pos] = make_int2(s, *reinterpret_cast<int*>(&h2));
    }
}

// ---------------- propagation, hfma2 accumulate, no shfl ------------------------
// warp per destination node. Lane ll (clamped to NLOAD-1) owns 4 halves
// [4*ll, 4*ll+4) of the row, loaded as one uint2. All lanes walk the edge
// list with uniform int2 loads (broadcast). 4 independent hfma2 chains.
// MODE 1: out(half) = relu((S in) @ W + b) per time slice (stride FSTRIDE).
// MODE 0: out(half) = S in (stride FSTRIDE).
template <int STRIDE_H, int NLOAD, int FIN_IN, int MODE>
__global__ __launch_bounds__(256) void kprop(const __half* __restrict__ in,
                                             __half* __restrict__ out,
                                             const int* __restrict__ rowp,
                                             const int* __restrict__ degv,
                                             const int2* __restrict__ edge,
                                             const float* __restrict__ dinv,
                                             const float* __restrict__ Wm,
                                             const float* __restrict__ bm, int n) {
    __shared__ float sAgg[MODE ? 8 : 1][MODE ? NLOAD * 4 : 4];
    __shared__ float sW[MODE ? FIN_IN * 16 : 1];
    __shared__ float sB[MODE ? 16 : 1];
    if (MODE) {
        for (int i = threadIdx.x; i < FIN_IN * 16; i += blockDim.x) sW[i] = Wm[i];
        if (threadIdx.x < 16) sB[threadIdx.x] = bm[threadIdx.x];
        __syncthreads();
    }
    int wwid = threadIdx.x >> 5;
    int node = (blockIdx.x << 3) + wwid;
    if (node >= n) return;
    int lane = threadIdx.x & 31;
    int ll = (lane < NLOAD) ? lane : (NLOAD - 1);   // clamp; extras discarded
    bool act = lane < NLOAD;

    __half2 zero2 = __float2half2_rn(0.f);
    __half2 a0x = zero2, a0y = zero2, a1x = zero2, a1y = zero2;
    __half2 a2x = zero2, a2y = zero2, a3x = zero2, a3y = zero2;

    int j = rowp[node];
    int end = j + degv[node];

    for (; j + 4 <= end; j += 4) {
        int2 e0 = __ldg(edge + j);
        int2 e1 = __ldg(edge + j + 1);
        int2 e2 = __ldg(edge + j + 2);
        int2 e3 = __ldg(edge + j + 3);
        uint2 q0 = __ldg((const uint2*)(in + (size_t)e0.x * STRIDE_H) + ll);
        uint2 q1 = __ldg((const uint2*)(in + (size_t)e1.x * STRIDE_H) + ll);
        uint2 q2 = __ldg((const uint2*)(in + (size_t)e2.x * STRIDE_H) + ll);
        uint2 q3 = __ldg((const uint2*)(in + (size_t)e3.x * STRIDE_H) + ll);
        __half2 w0 = bits_h2(e0.y), w1 = bits_h2(e1.y);
        __half2 w2 = bits_h2(e2.y), w3 = bits_h2(e3.y);
        a0x = __hfma2(w0, bits_h2u(q0.x), a0x);
        a0y = __hfma2(w0, bits_h2u(q0.y), a0y);
        a1x = __hfma2(w1, bits_h2u(q1.x), a1x);
        a1y = __hfma2(w1, bits_h2u(q1.y), a1y);
        a2x = __hfma2(w2, bits_h2u(q2.x), a2x);
        a2y = __hfma2(w2, bits_h2u(q2.y), a2y);
        a3x = __hfma2(w3, bits_h2u(q3.x), a3x);
        a3y = __hfma2(w3, bits_h2u(q3.y), a3y);
    }
    for (; j < end; j++) {
        int2 e0 = __ldg(edge + j);
        uint2 q0 = __ldg((const uint2*)(in + (size_t)e0.x * STRIDE_H) + ll);
        __half2 w0 = bits_h2(e0.y);
        a0x = __hfma2(w0, bits_h2u(q0.x), a0x);
        a0y = __hfma2(w0, bits_h2u(q0.y), a0y);
    }

    // merge chains in fp32 + fp32 self-loop
    float di = dinv[node];
    uint2 sq = __ldg((const uint2*)(in + (size_t)node * STRIDE_H) + ll);
    float2 s01 = __half22float2(bits_h2u(sq.x));
    float2 s23 = __half22float2(bits_h2u(sq.y));
    float2 c0, c1, c2, c3;
    c0 = __half22float2(a0x); c1 = __half22float2(a1x);
    c2 = __half22float2(a2x); c3 = __half22float2(a3x);
    float f0 = (c0.x + c1.x) + (c2.x + c3.x) + di * s01.x;
    float f1 = (c0.y + c1.y) + (c2.y + c3.y) + di * s01.y;
    c0 = __half22float2(a0y); c1 = __half22float2(a1y);
    c2 = __half22float2(a2y); c3 = __half22float2(a3y);
    float f2 = (c0.x + c1.x) + (c2.x + c3.x) + di * s23.x;
    float f3 = (c0.y + c1.y) + (c2.y + c3.y) + di * s23.y;

    if (!MODE) {
        if (act) {
            __half2 o01 = __floats2half2_rn(f0, f1);
            __half2 o23 = __floats2half2_rn(f2, f3);
            uint2 pk;
            pk.x = *reinterpret_cast<unsigned*>(&o01);
            pk.y = *reinterpret_cast<unsigned*>(&o23);
            *((uint2*)(out + (size_t)node * FSTRIDE) + lane) = pk;
        }
        return;
    }

    // stage the aggregate, then per-slice dense transform + relu + fp16 pack
    if (act) {
        float4 fv = make_float4(f0, f1, f2, f3);
        *(float4*)&sAgg[wwid][lane * 4] = fv;
    }
    __syncwarp();
    if (lane < 20) {
        int c = lane * 4;         // 20 lanes x 4 outputs = 80
        int t = c >> 4;
        int h = c & 15;
        float o0 = sB[h], o1 = sB[h + 1], o2 = sB[h + 2], o3 = sB[h + 3];
#pragma unroll
        for (int f = 0; f < FIN_IN; f++) {
            float a = sAgg[wwid][t * FIN_IN + f];
            o0 = fmaf(a, sW[f * 16 + h],     o0);
            o1 = fmaf(a, sW[f * 16 + h + 1], o1);
            o2 = fmaf(a, sW[f * 16 + h + 2], o2);
            o3 = fmaf(a, sW[f * 16 + h + 3], o3);
        }
        __half2 p01 = __floats2half2_rn(fmaxf(o0, 0.f), fmaxf(o1, 0.f));
        __half2 p23 = __floats2half2_rn(fmaxf(o2, 0.f), fmaxf(o3, 0.f));
        uint2 pk;
        pk.x = *reinterpret_cast<unsigned*>(&p01);
        pk.y = *reinterpret_cast<unsigned*>(&p23);
        *((uint2*)(out + (size_t)node * FSTRIDE) + lane) = pk;
    }
}

// ---------------- fold gate matmuls: M* = W* @ L*[0:16], B* = b*@L*[0:16] + l* ----
__global__ void kprepG(const float* Wz, const float* bz, const float* Wr, const float* br,
                       const float* Wh, const float* bh,
                       const float* Lz, const float* lz, const float* Lr, const float* lr,
                       const float* Lh, const float* lh) {
    int tid = threadIdx.x;  // 256
    int k = tid >> 4, h = tid & 15;
    float mz = 0.f, mr = 0.f, mh = 0.f;
#pragma unroll
    for (int j = 0; j < 16; j++) {
        mz = fmaf(Wz[k * 16 + j], Lz[j * 16 + h], mz);
        mr = fmaf(Wr[k * 16 + j], Lr[j * 16 + h], mr);
        mh = fmaf(Wh[k * 16 + j], Lh[j * 16 + h], mh);
    }
    g_Mz[tid] = mz; g_Mr[tid] = mr; g_Mh[tid] = mh;
    if (tid < 16) {
        float az = lz[tid], ar = lr[tid], ah = lh[tid];
#pragma unroll
        for (int j = 0; j < 16; j++) {
            az = fmaf(bz[j], Lz[j * 16 + tid], az);
            ar = fmaf(br[j], Lr[j * 16 + tid], ar);
            ah = fmaf(bh[j], Lh[j * 16 + tid], ah);
        }
        g_Bz[tid] = az; g_Br[tid] = ar; g_Bh[tid] = ah;
    }
}

// ---------------- GRU + attention pooling + FC + log_softmax ---------------------
#define GRU_NPB 96
__global__ __launch_bounds__(GRU_NPB) void kgru(const __half* __restrict__ P,
                                                const float* __restrict__ Lz,
                                                const float* __restrict__ Lr,
                                                const float* __restrict__ Lh,
                                                const float* __restrict__ att,
                                                const float* __restrict__ fcW,
                                                const float* __restrict__ fcb,
                                                float* __restrict__ out, int n) {
    __shared__ float sP[GRU_NPB * 81];
    __shared__ float sMz[256], sMr[256], sMh[256];
    __shared__ float sLz[256], sLr[256], sLh[256];
    __shared__ float sBz[16], sBr[16], sBh[16];
    __shared__ float sfcW[32], sfcb[2], sprob[TT];

    int tid = threadIdx.x;
    for (int i = tid; i < 256; i += GRU_NPB) {
        sMz[i] = g_Mz[i]; sMr[i] = g_Mr[i]; sMh[i] = g_Mh[i];
        sLz[i] = Lz[256 + i]; sLr[i] = Lr[256 + i]; sLh[i] = Lh[256 + i];
    }
    if (tid < 16) { sBz[tid] = g_Bz[tid]; sBr[tid] = g_Br[tid]; sBh[tid] = g_Bh[tid]; }
    if (tid < 32) sfcW[tid] = fcW[tid];
    if (tid < 2)  sfcb[tid] = fcb[tid];
    if (tid == 0) {
        float m = att[0];
        for (int t = 1; t < TT; t++) m = fmaxf(m, att[t]);
        float ex[TT]; float s = 0.f;
        for (int t = 0; t < TT; t++) { ex[t] = expf(att[t] - m); s += ex[t]; }
        for (int t = 0; t < TT; t++) sprob[t] = ex[t] / s;
    }
    int base = blockIdx.x * GRU_NPB;
    for (int i = tid; i < GRU_NPB * (FSTRIDE / 2); i += GRU_NPB) {
        int nd = i / (FSTRIDE / 2), c2 = i - nd * (FSTRIDE / 2);
        int g = base + nd;
        float2 f = make_float2(0.f, 0.f);
        if (g < n) {
            unsigned u = __ldg((const unsigned*)(P + (size_t)g * FSTRIDE) + c2);
            f = __half22float2(bits_h2u(u));
        }
        sP[nd * 81 + 2 * c2]     = f.x;
        sP[nd * 81 + 2 * c2 + 1] = f.y;
    }
    __syncthreads();

    int node = base + tid;
    if (node >= n) return;
    const float* myP = &sP[tid * 81];

    float H[16], Hacc[16];
#pragma unroll
    for (int h = 0; h < 16; h++) { H[h] = 0.f; Hacc[h] = 0.f; }

#pragma unroll 1
    for (int t = 0; t < TT; t++) {
        float p[16];
#pragma unroll
        for (int k = 0; k < 16; k++) p[k] = myP[t * 16 + k];

        float a[16];
#pragma unroll
        for (int h = 0; h < 16; h++) a[h] = sBz[h];
#pragma unroll
        for (int k = 0; k < 16; k++) {
            float pk = p[k], hk = H[k];
#pragma unroll
            for (int h = 0; h < 16; h++)
                a[h] += pk * sMz[k * 16 + h] + hk * sLz[k * 16 + h];
        }
        float Zg[16];
#pragma unroll
        for (int h = 0; h < 16; h++) Zg[h] = fast_sig(a[h]);

#pragma unroll
        for (int h = 0; h < 16; h++) a[h] = sBr[h];
#pragma unroll
        for (int k = 0; k < 16; k++) {
            float pk = p[k], hk = H[k];
#pragma unroll
            for (int h = 0; h < 16; h++)
                a[h] += pk * sMr[k * 16 + h] + hk * sLr[k * 16 + h];
        }
        float Rg[16];
#pragma unroll
        for (int h = 0; h < 16; h++) Rg[h] = fast_sig(a[h]);

#pragma unroll
        for (int h = 0; h < 16; h++) a[h] = sBh[h];
#pragma unroll
        for (int k = 0; k < 16; k++) {
            float pk = p[k], hr = H[k] * Rg[k];
#pragma unroll
            for (int h = 0; h < 16; h++)
                a[h] += pk * sMh[k * 16 + h] + hr * sLh[k * 16 + h];
        }
#pragma unroll
        for (int h = 0; h < 16; h++) {
            float ht = fast_tanh(a[h]);
            H[h] = Zg[h] * H[h] + (1.f - Zg[h]) * ht;
            Hacc[h] = fmaf(sprob[t], H[h], Hacc[h]);
        }
    }

    float l0 = sfcb[0], l1 = sfcb[1];
#pragma unroll
    for (int h = 0; h < 16; h++) {
        l0 = fmaf(Hacc[h], sfcW[h * 2 + 0], l0);
        l1 = fmaf(Hacc[h], sfcW[h * 2 + 1], l1);
    }
    float m = fmaxf(l0, l1);
    float lse = m + logf(expf(l0 - m) + expf(l1 - m));
    out[(size_t)node * 2 + 0] = l0 - lse;
    out[(size_t)node * 2 + 1] = l1 - lse;
}

// ---------------- launch ----------------
extern "C" void kernel_launch(void* const* d_in, const int* in_sizes, int n_in,
                              void* d_out, int out_size) {
    const float* x   = (const float*)d_in[0];
    const int*   src = (const int*)d_in[1];
    const int*   dst = (const int*)d_in[2];
    const float* W1  = (const float*)d_in[3];
    const float* b1  = (const float*)d_in[4];
    const float* W2  = (const float*)d_in[5];
    const float* b2  = (const float*)d_in[6];
    const float* Wz  = (const float*)d_in[7];
    const float* bz  = (const float*)d_in[8];
    const float* Wr  = (const float*)d_in[9];
    const float* br  = (const float*)d_in[10];
    const float* Wh  = (const float*)d_in[11];
    const float* bh  = (const float*)d_in[12];
    const float* Lz  = (const float*)d_in[13];
    const float* lz  = (const float*)d_in[14];
    const float* Lr  = (const float*)d_in[15];
    const float* lr  = (const float*)d_in[16];
    const float* Lh  = (const float*)d_in[17];
    const float* lh  = (const float*)d_in[18];
    const float* att = (const float*)d_in[19];
    const float* fcW = (const float*)d_in[20];
    const float* fcb = (const float*)d_in[21];

    int n = in_sizes[0] / (TT * FIN);
    int e = in_sizes[1];

    void* p;
    cudaGetSymbolAddress(&p, g_cnt);     int*    cnt    = (int*)p;
    cudaGetSymbolAddress(&p, g_deg);     int*    degv   = (int*)p;
    cudaGetSymbolAddress(&p, g_row);     int*    rowp   = (int*)p;
    cudaGetSymbolAddress(&p, g_cursor);  int*    cursor = (int*)p;
    cudaGetSymbolAddress(&p, g_dis);     float*  dis    = (float*)p;
    cudaGetSymbolAddress(&p, g_dinv);    float*  dinv   = (float*)p;
    cudaGetSymbolAddress(&p, g_edge);    int2*   edge   = (int2*)p;
    cudaGetSymbolAddress(&p, g_xT);      __half* xT     = (__half*)p;
    cudaGetSymbolAddress(&p, g_h1);      __half* h1     = (__half*)p;
    cudaGetSymbolAddress(&p, g_feats);   __half* feats  = (__half*)p;
    cudaGetSymbolAddress(&p, g_P);       __half* P      = (__half*)p;

    int nb256_n = (n + 255) / 256;
    int nb256_e = (e + 255) / 256;
    int prep0_threads = (e > n * XREAL) ? e : n * XREAL;
    int prop_blocks = (n + 7) / 8;

    // 0: fused degree count + x transpose (fp16)
    kprep0<<<(prep0_threads + 255) / 256, 256>>>(dst, cnt, x, xT, n, e);
    // 1: offsets + norms
    koffsets<<<nb256_n, 256>>>(cnt, n);
    // 2: fill edge list (weights packed half2)
    kfill<<<nb256_e, 256>>>(src, dst, dis, cursor, edge, e);
    // 3: h1 = relu((S x) @ W1 + b1)      <-- profiled slot
    kprop<XSTRIDE, 13, FIN, 1><<<prop_blocks, 256>>>(xT, h1, rowp, degv, edge, dinv, W1, b1, n);
    // 4: feats = relu((S h1) @ W2 + b2)
    kprop<FSTRIDE, 20, HID, 1><<<prop_blocks, 256>>>(h1, feats, rowp, degv, edge, dinv, W2, b2, n);
    // 5: P = S feats (half out, shared by all three GRU gate GCNs)
    kprop<FSTRIDE, 20, HID, 0><<<prop_blocks, 256>>>(feats, P, rowp, degv, edge, dinv, W2, b2, n);
    // 6: fold GRU gate weights
    kprepG<<<1, 256>>>(Wz, bz, Wr, br, Wh, bh, Lz, lz, Lr, lr, Lh, lh);
    // 7: GRU + attention + FC + log_softmax
    kgru<<<(n + GRU_NPB - 1) / GRU_NPB, GRU_NPB>>>(P, Lz, Lr, Lh, att, fcW, fcb,
                                                   (float*)d_out, n);
}